// round 10
// baseline (speedup 1.0000x reference)
#include <cuda_runtime.h>
#include <cuda_bf16.h>
#include <math.h>
#include <stdint.h>

#define NG 1024
#define HD 128
#define ET 500000
#define NN 100000
#define SQRT_H 11.313708498984761f

#define TM 128                 // edges per CTA
#define KP2 136                // padded A row pitch (bf16 elems), K=128
#define EDGE_BLKS ((ET + TM - 1) / TM)   // 3907
#define NT_BLKS ((NN + TM - 1) / TM)     // 782
#define NKS 24

// ---------------- scratch (device globals; no allocation allowed) ----------------
__device__ unsigned g_tmax[NN];
__device__ float    g_tsum[NN];
__device__ float    g_logits[ET];
__device__ float    g_logpb[NG];
__device__ int      g_selcnt[NG];
__device__ int      g_mflag;
__device__ __align__(16) unsigned g_Bf0[NKS * 16 * 32];
__device__ __align__(16) unsigned g_Bf1[NKS * 16 * 32];
// folded-LN precomputations
__device__ __align__(16) float g_NodeT[NN * HD];   // (node ⊙ g_tail) @ W_tail  (51MB)
__device__ __align__(16) float g_QT[NG * HD];      // (q ⊙ g_mid) @ W_mid (f32 exact)
__device__ float g_U[HD];       // sum_k g_k W[k,n]  (all 384)
__device__ float g_Vb[HD];      // sum_k b_k W[k,n] + bb1[n]
__device__ float g_qsum[NG], g_qss[NG];
__device__ float g_nsum[NN], g_nss[NN];

// ---------------- helpers ----------------
__device__ __forceinline__ float gelu_f(float x){
    return 0.5f * x * (1.0f + erff(x * 0.70710678118654752440f));
}
__device__ __forceinline__ float gelu_t(float x){
    float u = fmaf(0.044715f * x * x, x, x) * 0.7978845608028654f;
    float th;
    asm("tanh.approx.f32 %0, %1;" : "=f"(th) : "f"(u));
    return 0.5f * x * (1.0f + th);
}
__device__ __forceinline__ unsigned fenc(float f){
    unsigned b = __float_as_uint(f);
    return (b & 0x80000000u) ? ~b : (b | 0x80000000u);
}
__device__ __forceinline__ float fdec(unsigned u){
    return __uint_as_float((u & 0x80000000u) ? (u & 0x7FFFFFFFu) : ~u);
}
__device__ __forceinline__ float4 ld4(const float* p){ return *(const float4*)p; }

__device__ __forceinline__ uint32_t smem_u32(const void* p){
    uint32_t a;
    asm("{ .reg .u64 t; cvta.to.shared.u64 t, %1; cvt.u32.u64 %0, t; }" : "=r"(a) : "l"(p));
    return a;
}
__device__ __forceinline__ unsigned packbf2(float lo, float hi){
    __nv_bfloat162 v;
    v.x = __float2bfloat16(lo);
    v.y = __float2bfloat16(hi);
    return *(unsigned*)&v;
}
__device__ __forceinline__ void ldm_x4(uint32_t* r, uint32_t addr){
    asm volatile("ldmatrix.sync.aligned.m8n8.x4.shared.b16 {%0,%1,%2,%3}, [%4];"
                 : "=r"(r[0]), "=r"(r[1]), "=r"(r[2]), "=r"(r[3]) : "r"(addr));
}
__device__ __forceinline__ void mma16816(float* d, const uint32_t* a,
                                         uint32_t b0, uint32_t b1){
    asm volatile(
        "mma.sync.aligned.m16n8k16.row.col.f32.bf16.bf16.f32 "
        "{%0,%1,%2,%3}, {%4,%5,%6,%7}, {%8,%9}, {%0,%1,%2,%3};"
        : "+f"(d[0]), "+f"(d[1]), "+f"(d[2]), "+f"(d[3])
        : "r"(a[0]), "r"(a[1]), "r"(a[2]), "r"(a[3]), "r"(b0), "r"(b1));
}

__device__ __forceinline__ float bsum256(float v, float* red){
    #pragma unroll
    for (int o = 16; o > 0; o >>= 1) v += __shfl_xor_sync(0xFFFFFFFFu, v, o);
    int w = threadIdx.x >> 5;
    if ((threadIdx.x & 31) == 0) red[w] = v;
    __syncthreads();
    if (threadIdx.x == 0){
        float s = red[0];
        #pragma unroll
        for (int i = 1; i < 8; i++) s += red[i];
        red[0] = s;
    }
    __syncthreads();
    float r = red[0];
    __syncthreads();
    return r;
}

// ---------------- prep: init scratch + mask detect + W fragments ----------------
__global__ void k_prep(const unsigned* __restrict__ mask, const float* __restrict__ bw1){
    int i = blockIdx.x * blockDim.x + threadIdx.x;
    if (i < NN){ g_tmax[i] = 0u; g_tsum[i] = 0.0f; }
    if (i < NG){ g_logpb[i] = 0.0f; g_selcnt[i] = 0; }
    if (i < 4096){
        unsigned w = mask[i];
        int f = (w == 0x3F800000u) ? 1 : ((w > 1u) ? 2 : 0);
        if (f) atomicOr(&g_mflag, f);
    }
    if (i < NKS * 512){
        int lane = i & 31, nt = (i >> 5) & 15, s = i >> 9;
        int n  = nt * 8 + (lane >> 2);
        int k0 = s * 16 + (lane & 3) * 2;
        int o  = s * 512 + (nt >> 2) * 128 + lane * 4 + (nt & 3);
        g_Bf0[o] = packbf2(bw1[k0 * HD + n],       bw1[(k0 + 1) * HD + n]);
        g_Bf1[o] = packbf2(bw1[(k0 + 8) * HD + n], bw1[(k0 + 9) * HD + n]);
    }
}

// ---------------- pre2: NodeT tiles (HMMA), QT per graph, U/Vb ----------------
__global__ __launch_bounds__(256, 2) void k_pre2(
    const float* __restrict__ node, const float* __restrict__ ques,
    const float* __restrict__ blng, const float* __restrict__ blnb,
    const float* __restrict__ bw1,  const float* __restrict__ bb1)
{
    extern __shared__ char sm[];
    int t = threadIdx.x, lane = t & 31, w = t >> 5;

    if (blockIdx.x >= NT_BLKS + NG){
        // ---- U / Vb ----
        if (t < HD){
            float u = 0.f, vb = 0.f;
            for (int k = 0; k < 384; k++){
                float wv = bw1[k * HD + t];
                u  = fmaf(blng[k], wv, u);
                vb = fmaf(blnb[k], wv, vb);
            }
            g_U[t] = u;
            g_Vb[t] = vb + bb1[t];
        }
        return;
    }

    if (blockIdx.x >= NT_BLKS){
        // ---- QT[g] + qsum/qss (f32 exact) ----
        float* qg  = (float*)sm;          // 128
        float* red = qg + 128;            // 8
        int g = blockIdx.x - NT_BLKS;
        float qv = (t < HD) ? ques[(size_t)g * HD + t] : 0.0f;
        if (t < HD) qg[t] = qv * blng[128 + t];
        float qs  = bsum256(qv, red);
        float qss = bsum256(qv * qv, red);
        if (t == 0){ g_qsum[g] = qs; g_qss[g] = qss; }
        __syncthreads();
        if (t < HD){
            float a0 = 0.f, a1 = 0.f, a2 = 0.f, a3 = 0.f;
            #pragma unroll 4
            for (int k = 0; k < HD; k += 4){
                a0 = fmaf(qg[k],     bw1[(128 + k) * HD + t],     a0);
                a1 = fmaf(qg[k + 1], bw1[(129 + k) * HD + t],     a1);
                a2 = fmaf(qg[k + 2], bw1[(130 + k) * HD + t],     a2);
                a3 = fmaf(qg[k + 3], bw1[(131 + k) * HD + t],     a3);
            }
            g_QT[(size_t)g * HD + t] = (a0 + a1) + (a2 + a3);
        }
        return;
    }

    // ---- NodeT tile: 128 node rows, K=128 (tail W, B ksteps 16..23) ----
    __nv_bfloat16* As = (__nv_bfloat16*)sm;
    int v0 = blockIdx.x * TM;
    int gid = lane >> 2, tig = lane & 3;

    for (int i = 0; i < 16; i++){
        int el = w * 16 + i;
        int v  = v0 + el;
        int k  = lane * 4;
        __nv_bfloat16* xr = As + el * KP2;
        if (v >= NN){
            *(unsigned*)(xr + k) = 0; *(unsigned*)(xr + k + 2) = 0;
            continue;
        }
        float4 a = ld4(node + (size_t)v * HD + k);
        float4 g2 = ld4(blng + 256 + k);
        float s  = a.x + a.y + a.z + a.w;
        float ss = a.x*a.x + a.y*a.y + a.z*a.z + a.w*a.w;
        #pragma unroll
        for (int o = 16; o > 0; o >>= 1){
            s  += __shfl_xor_sync(0xFFFFFFFFu, s,  o);
            ss += __shfl_xor_sync(0xFFFFFFFFu, ss, o);
        }
        if (lane == 0){ g_nsum[v] = s; g_nss[v] = ss; }
        *(unsigned*)(xr + k)     = packbf2(a.x * g2.x, a.y * g2.y);
        *(unsigned*)(xr + k + 2) = packbf2(a.z * g2.z, a.w * g2.w);
    }
    __syncthreads();

    int mbase = (w & 3) * 32;
    int qb    = (w >> 2) * 2;
    int nbt   = qb * 4;
    float acc[2][8][4];
    #pragma unroll
    for (int mt = 0; mt < 2; mt++)
        #pragma unroll
        for (int j = 0; j < 8; j++)
            #pragma unroll
            for (int r = 0; r < 4; r++) acc[mt][j][r] = 0.0f;

    uint32_t As_u = smem_u32(As);
    int arow = mbase + (lane & 15);
    int acol = (lane >> 4) * 8;
    const uint4* B0 = (const uint4*)g_Bf0 + qb * 32 + lane;
    const uint4* B1 = (const uint4*)g_Bf1 + qb * 32 + lane;

    #pragma unroll 2
    for (int sl = 0; sl < 8; sl++){
        int s = sl + 16;
        uint4 u00 = __ldg(B0 + s * 128);
        uint4 u01 = __ldg(B0 + s * 128 + 32);
        uint4 u10 = __ldg(B1 + s * 128);
        uint4 u11 = __ldg(B1 + s * 128 + 32);
        uint32_t a0[4], a1[4];
        uint32_t ad = As_u + (uint32_t)((arow * KP2 + sl * 16 + acol) * 2);
        ldm_x4(a0, ad);
        ldm_x4(a1, ad + (uint32_t)(16 * KP2 * 2));
        mma16816(acc[0][0], a0, u00.x, u10.x);  mma16816(acc[1][0], a1, u00.x, u10.x);
        mma16816(acc[0][1], a0, u00.y, u10.y);  mma16816(acc[1][1], a1, u00.y, u10.y);
        mma16816(acc[0][2], a0, u00.z, u10.z);  mma16816(acc[1][2], a1, u00.z, u10.z);
        mma16816(acc[0][3], a0, u00.w, u10.w);  mma16816(acc[1][3], a1, u00.w, u10.w);
        mma16816(acc[0][4], a0, u01.x, u11.x);  mma16816(acc[1][4], a1, u01.x, u11.x);
        mma16816(acc[0][5], a0, u01.y, u11.y);  mma16816(acc[1][5], a1, u01.y, u11.y);
        mma16816(acc[0][6], a0, u01.z, u11.z);  mma16816(acc[1][6], a1, u01.z, u11.z);
        mma16816(acc[0][7], a0, u01.w, u11.w);  mma16816(acc[1][7], a1, u01.w, u11.w);
    }

    #pragma unroll
    for (int mt = 0; mt < 2; mt++)
        #pragma unroll
        for (int rr = 0; rr < 2; rr++){
            int row = mbase + mt * 16 + gid + rr * 8;
            int v = v0 + row;
            if (v < NN){
                float* dst = g_NodeT + (size_t)v * HD;
                #pragma unroll
                for (int j = 0; j < 8; j++){
                    int n0 = (nbt + j) * 8 + tig * 2;
                    float2 o2 = make_float2(acc[mt][j][rr*2], acc[mt][j][rr*2 + 1]);
                    *(float2*)(dst + n0) = o2;
                }
            }
        }
}

// ---------------- fused main kernel: graph blocks [0,NG) + edge blocks ----------------
// dyn smem (edge): A[128][136] bf16 (34816) | sMean 512 | sRstd 512 | sGb 512 |
//                  tgt 512 | sU 512 | sVb 512 | sW2 512 | part 1024
#define OFF_A    0
#define OFF_MEAN 34816
#define OFF_RSTD 35328
#define OFF_GB   35840
#define OFF_TGT  36352
#define OFF_U    36864
#define OFF_VB   37376
#define OFF_W2   37888
#define OFF_PART 38400
#define MAIN_SMEM 39424

__global__ __launch_bounds__(256, 2) void k_main(
    const float* __restrict__ node, const float* __restrict__ ques,
    const float* __restrict__ etok,
    const float* __restrict__ blng,
    const float* __restrict__ bw2,  const float* __restrict__ bb2,
    const int* __restrict__ ebatch, const int* __restrict__ eidx,
    const float* __restrict__ ln1g, const float* __restrict__ ln1b,
    const float* __restrict__ zw1,  const float* __restrict__ zb1,
    const float* __restrict__ zw2,  const float* __restrict__ zb2,
    const float* __restrict__ cw1,  const float* __restrict__ cb1,
    const float* __restrict__ cw2,  const float* __restrict__ cb2,
    const int* __restrict__ locals, const int* __restrict__ ptr,
    float* __restrict__ out)
{
    extern __shared__ char sm[];
    int t = threadIdx.x, lane = t & 31, w = t >> 5;

    if (blockIdx.x < NG){
        // ================= graph path (unchanged) =================
        float* xs  = (float*)sm;
        float* hs  = xs + 256;
        float* red = hs + 128;
        float* sc  = red + 8;
        int*  locs = (int*)(sc + 32);

        int g = blockIdx.x;
        bool act = t < 128;
        float q = act ? ques[g * HD + t] : 0.0f;
        if (act) xs[HD + t] = q;

        int p0 = ptr[g], p1 = ptr[g + 1];
        int cnt = p1 - p0; if (cnt > 32) cnt = 32;

        float4 qv = ld4(ques + (size_t)g * HD + lane * 4);
        for (int i = w; i < cnt; i += 8){
            int loc = locals[p0 + i];
            float4 nv = ld4(node + (size_t)loc * HD + lane * 4);
            float d = nv.x*qv.x + nv.y*qv.y + nv.z*qv.z + nv.w*qv.w;
            #pragma unroll
            for (int o = 16; o > 0; o >>= 1) d += __shfl_xor_sync(0xFFFFFFFFu, d, o);
            if (lane == 0){ sc[i] = d / SQRT_H; locs[i] = loc; }
        }
        __syncthreads();

        if (act){
            float m = -1e30f;
            for (int i = 0; i < cnt; i++) m = fmaxf(m, sc[i]);
            float den = 0.0f;
            for (int i = 0; i < cnt; i++) den += expf(sc[i] - m);
            float summ = 0.0f;
            for (int i = 0; i < cnt; i++){
                float a = expf(sc[i] - m) / den;
                summ += a * node[(size_t)locs[i] * HD + t];
            }
            xs[t] = summ;
        }
        __syncthreads();

        float ctx = 0.0f;
        if (act){
            float a0 = 0.f, a1 = 0.f, a2 = 0.f, a3 = 0.f;
            #pragma unroll 4
            for (int k = 0; k < 2 * HD; k += 4){
                a0 = fmaf(xs[k],     cw1[k * HD + t],       a0);
                a1 = fmaf(xs[k + 1], cw1[(k + 1) * HD + t], a1);
                a2 = fmaf(xs[k + 2], cw1[(k + 2) * HD + t], a2);
                a3 = fmaf(xs[k + 3], cw1[(k + 3) * HD + t], a3);
            }
            hs[t] = gelu_f(cb1[t] + ((a0 + a1) + (a2 + a3)));
        }
        __syncthreads();
        if (act){
            float a0 = 0.f, a1 = 0.f, a2 = 0.f, a3 = 0.f;
            #pragma unroll 4
            for (int k = 0; k < HD; k += 4){
                a0 = fmaf(hs[k],     cw2[k * HD + t],       a0);
                a1 = fmaf(hs[k + 1], cw2[(k + 1) * HD + t], a1);
                a2 = fmaf(hs[k + 2], cw2[(k + 2) * HD + t], a2);
                a3 = fmaf(hs[k + 3], cw2[(k + 3) * HD + t], a3);
            }
            ctx = cb2[t] + ((a0 + a1) + (a2 + a3));
        }

        float mean = bsum256(act ? ctx : 0.0f, red) * (1.0f / HD);
        float msq  = bsum256(act ? ctx * ctx : 0.0f, red) * (1.0f / HD);
        float rstd = rsqrtf(msq - mean * mean + 1e-5f);
        if (act) xs[t] = (ctx - mean) * rstd * ln1g[t] + ln1b[t];
        __syncthreads();

        float hz = 0.0f;
        if (act){
            float a0 = 0.f, a1 = 0.f, a2 = 0.f, a3 = 0.f;
            #pragma unroll 4
            for (int k = 0; k < HD; k += 4){
                a0 = fmaf(xs[k],     zw1[k * HD + t],       a0);
                a1 = fmaf(xs[k + 1], zw1[(k + 1) * HD + t], a1);
                a2 = fmaf(xs[k + 2], zw1[(k + 2) * HD + t], a2);
                a3 = fmaf(xs[k + 3], zw1[(k + 3) * HD + t], a3);
            }
            hz = gelu_f(zb1[t] + ((a0 + a1) + (a2 + a3))) * zw2[t];
        }
        float lz = bsum256(act ? hz : 0.0f, red);
        if (t == 0) out[g * 3 + 0] = lz + zb2[0];
        return;
    }

    // ================= edge path (folded LN, K=128) =================
    __nv_bfloat16* As = (__nv_bfloat16*)(sm + OFF_A);
    float* sMean = (float*)(sm + OFF_MEAN);
    float* sRstd = (float*)(sm + OFF_RSTD);
    int*   sGb   = (int*)(sm + OFF_GB);
    int*   tgt_s = (int*)(sm + OFF_TGT);
    float* sU    = (float*)(sm + OFF_U);
    float* sVb   = (float*)(sm + OFF_VB);
    float* sW2   = (float*)(sm + OFF_W2);
    float* part  = (float*)(sm + OFF_PART);

    int gid = lane >> 2, tig = lane & 3;
    int e0 = (blockIdx.x - NG) * TM;

    if (t < HD){ sU[t] = g_U[t]; sVb[t] = g_Vb[t]; sW2[t] = bw2[t]; }

    // per-edge index + precomputed-sum prefetch
    int myidx = 0; float myS = 0.f, mySS = 0.f;
    {
        int ei = e0 + w * 16 + (lane & 15);
        if (ei < ET){
            if (lane < 16){
                myidx = ebatch[ei];
                myS = g_qsum[myidx]; mySS = g_qss[myidx];
            } else {
                myidx = eidx[ET + ei];
                myS = g_nsum[myidx]; mySS = g_nss[myidx];
            }
        }
        if (lane < 16) sGb[w * 16 + lane] = myidx;
        else           tgt_s[w * 16 + (lane - 16)] = myidx;
    }

    // A: etok ⊙ g0 -> bf16; mean/rstd from scalar sums
    #pragma unroll 4
    for (int i = 0; i < 16; i++){
        int el = w * 16 + i;
        int e  = e0 + el;
        int k  = lane * 4;
        __nv_bfloat16* xr = As + el * KP2;
        if (e >= ET){
            *(unsigned*)(xr + k) = 0; *(unsigned*)(xr + k + 2) = 0;
            if (lane == 0){ sMean[el] = 0.f; sRstd[el] = 1.f; }
            continue;
        }
        float4 a  = ld4(etok + (size_t)e * HD + k);
        float4 g0 = ld4(blng + k);
        float s  = a.x + a.y + a.z + a.w;
        float ss = a.x*a.x + a.y*a.y + a.z*a.z + a.w*a.w;
        #pragma unroll
        for (int o = 16; o > 0; o >>= 1){
            s  += __shfl_xor_sync(0xFFFFFFFFu, s,  o);
            ss += __shfl_xor_sync(0xFFFFFFFFu, ss, o);
        }
        float qs  = __shfl_sync(0xFFFFFFFFu, myS,  i);
        float qss = __shfl_sync(0xFFFFFFFFu, mySS, i);
        float ns  = __shfl_sync(0xFFFFFFFFu, myS,  16 + i);
        float nss = __shfl_sync(0xFFFFFFFFu, mySS, 16 + i);
        float mean = (s + qs + ns) * (1.0f / 384.0f);
        float var  = (ss + qss + nss) * (1.0f / 384.0f) - mean * mean;
        float rstd = rsqrtf(var + 1e-5f);
        if (lane == 0){ sMean[el] = mean; sRstd[el] = rstd; }
        *(unsigned*)(xr + k)     = packbf2(a.x * g0.x, a.y * g0.y);
        *(unsigned*)(xr + k + 2) = packbf2(a.z * g0.z, a.w * g0.w);
    }
    __syncthreads();

    // HMMA mainloop: K=128 (8 ksteps)
    int mbase = (w & 3) * 32;
    int qb    = (w >> 2) * 2;
    int nbt   = qb * 4;
    float acc[2][8][4];
    #pragma unroll
    for (int mt = 0; mt < 2; mt++)
        #pragma unroll
        for (int j = 0; j < 8; j++)
            #pragma unroll
            for (int r = 0; r < 4; r++) acc[mt][j][r] = 0.0f;

    uint32_t As_u = smem_u32(As);
    int arow = mbase + (lane & 15);
    int acol = (lane >> 4) * 8;
    const uint4* B0 = (const uint4*)g_Bf0 + qb * 32 + lane;
    const uint4* B1 = (const uint4*)g_Bf1 + qb * 32 + lane;

    #pragma unroll 2
    for (int s = 0; s < 8; s++){
        uint4 u00 = __ldg(B0 + s * 128);
        uint4 u01 = __ldg(B0 + s * 128 + 32);
        uint4 u10 = __ldg(B1 + s * 128);
        uint4 u11 = __ldg(B1 + s * 128 + 32);
        uint32_t a0[4], a1[4];
        uint32_t ad = As_u + (uint32_t)((arow * KP2 + s * 16 + acol) * 2);
        ldm_x4(a0, ad);
        ldm_x4(a1, ad + (uint32_t)(16 * KP2 * 2));
        mma16816(acc[0][0], a0, u00.x, u10.x);  mma16816(acc[1][0], a1, u00.x, u10.x);
        mma16816(acc[0][1], a0, u00.y, u10.y);  mma16816(acc[1][1], a1, u00.y, u10.y);
        mma16816(acc[0][2], a0, u00.z, u10.z);  mma16816(acc[1][2], a1, u00.z, u10.z);
        mma16816(acc[0][3], a0, u00.w, u10.w);  mma16816(acc[1][3], a1, u00.w, u10.w);
        mma16816(acc[0][4], a0, u01.x, u11.x);  mma16816(acc[1][4], a1, u01.x, u11.x);
        mma16816(acc[0][5], a0, u01.y, u11.y);  mma16816(acc[1][5], a1, u01.y, u11.y);
        mma16816(acc[0][6], a0, u01.z, u11.z);  mma16816(acc[1][6], a1, u01.z, u11.z);
        mma16816(acc[0][7], a0, u01.w, u11.w);  mma16816(acc[1][7], a1, u01.w, u11.w);
    }

    // epilogue: add NodeT + QT pieces, LN fold, GELU, dot(w2)
    int half = w >> 2;
    #pragma unroll
    for (int mt = 0; mt < 2; mt++){
        #pragma unroll
        for (int rr = 0; rr < 2; rr++){
            int row = mbase + mt * 16 + gid + rr * 8;
            float mean = sMean[row], rstd = sRstd[row];
            const float* ntp = g_NodeT + (size_t)tgt_s[row] * HD;
            const float* qtp = g_QT   + (size_t)sGb[row]   * HD;
            float p = 0.0f;
            #pragma unroll
            for (int j = 0; j < 8; j++){
                int n0 = (nbt + j) * 8 + tig * 2;
                float2 nt = *(const float2*)(ntp + n0);
                float2 qt = *(const float2*)(qtp + n0);
                float a0 = acc[mt][j][rr*2],     a1 = acc[mt][j][rr*2 + 1];
                float pre0 = rstd * (a0 + nt.x + qt.x - mean * sU[n0])     + sVb[n0];
                float pre1 = rstd * (a1 + nt.y + qt.y - mean * sU[n0 + 1]) + sVb[n0 + 1];
                p += gelu_t(pre0) * sW2[n0] + gelu_t(pre1) * sW2[n0 + 1];
            }
            p += __shfl_xor_sync(0xFFFFFFFFu, p, 1);
            p += __shfl_xor_sync(0xFFFFFFFFu, p, 2);
            if (tig == 0) part[half * TM + row] = p;
        }
    }
    __syncthreads();

    if (w < 4){
        int el = w * 32 + lane;
        int e  = e0 + el;
        if (e < ET){
            float lg = part[el] + part[TM + el] + bb2[0];
            g_logits[e] = lg;
            atomicMax(&g_tmax[tgt_s[el]], fenc(lg));
        }
    }
}

// ---------------- segment softmax passes ----------------
__global__ __launch_bounds__(256) void k_pass2(const int* __restrict__ eidx){
    int e = (blockIdx.x * blockDim.x + threadIdx.x) * 4;
    if (e >= ET) return;
    int4   tg = *(const int4*)(eidx + ET + e);
    float4 lg = *(const float4*)(g_logits + e);
    float m0 = fdec(g_tmax[tg.x]);
    float m1 = fdec(g_tmax[tg.y]);
    float m2 = fdec(g_tmax[tg.z]);
    float m3 = fdec(g_tmax[tg.w]);
    float4 sh = make_float4(lg.x - m0, lg.y - m1, lg.z - m2, lg.w - m3);
    *(float4*)(g_logits + e) = sh;
    atomicAdd(&g_tsum[tg.x], expf(sh.x));
    atomicAdd(&g_tsum[tg.y], expf(sh.y));
    atomicAdd(&g_tsum[tg.z], expf(sh.z));
    atomicAdd(&g_tsum[tg.w], expf(sh.w));
}

__global__ void k_log(){
    int i = blockIdx.x * blockDim.x + threadIdx.x;
    if (i < NN) g_tsum[i] = logf(g_tsum[i]);
}

__global__ __launch_bounds__(256) void k_pass3(const int* __restrict__ eidx,
                                               const int* __restrict__ ebatch,
                                               const void* __restrict__ mask){
    int lane = threadIdx.x & 31;
    int e = (blockIdx.x * blockDim.x + threadIdx.x) * 4;
    if (e >= ET) return;
    int fl = g_mflag;
    int mode = (fl & 1) ? 2 : ((fl & 2) ? 0 : 1);

    int sel[4];
    if (mode == 0){
        uchar4 mv = *(const uchar4*)((const unsigned char*)mask + e);
        sel[0] = mv.x != 0; sel[1] = mv.y != 0; sel[2] = mv.z != 0; sel[3] = mv.w != 0;
    } else if (mode == 1){
        int4 mv = *(const int4*)((const int*)mask + e);
        sel[0] = mv.x != 0; sel[1] = mv.y != 0; sel[2] = mv.z != 0; sel[3] = mv.w != 0;
    } else {
        float4 mv = *(const float4*)((const float*)mask + e);
        sel[0] = mv.x != 0.f; sel[1] = mv.y != 0.f; sel[2] = mv.z != 0.f; sel[3] = mv.w != 0.f;
    }

    int4   tg = *(const int4*)(eidx + ET + e);
    int4   gb = *(const int4*)(ebatch + e);
    float4 sh = *(const float4*)(g_logits + e);

    float lp[4];
    lp[0] = sel[0] ? (sh.x - g_tsum[tg.x]) : 0.0f;
    lp[1] = sel[1] ? (sh.y - g_tsum[tg.y]) : 0.0f;
    lp[2] = sel[2] ? (sh.z - g_tsum[tg.z]) : 0.0f;
    lp[3] = sel[3] ? (sh.w - g_tsum[tg.w]) : 0.0f;
    int gbs[4] = {gb.x, gb.y, gb.z, gb.w};

    float v = 0.0f; int c = 0;
    int key = gbs[0];
    #pragma unroll
    for (int j = 0; j < 4; j++){
        if (gbs[j] == key){ v += lp[j]; c += sel[j]; }
        else if (sel[j]){
            atomicAdd(&g_logpb[gbs[j]], lp[j]);
            atomicAdd(&g_selcnt[gbs[j]], 1);
        }
    }

    #pragma unroll
    for (int off = 1; off < 32; off <<= 1){
        float ov = __shfl_down_sync(0xFFFFFFFFu, v, off);
        int   oc = __shfl_down_sync(0xFFFFFFFFu, c, off);
        int   ok = __shfl_down_sync(0xFFFFFFFFu, key, off);
        if (lane + off < 32 && ok == key){ v += ov; c += oc; }
    }
    int prevk = __shfl_up_sync(0xFFFFFFFFu, key, 1);
    bool leader = (lane == 0) || (prevk != key);
    if (leader && c > 0){
        atomicAdd(&g_logpb[key], v);
        atomicAdd(&g_selcnt[key], c);
    }
}

// ---------------- final ----------------
__global__ __launch_bounds__(1024) void k_final(float* __restrict__ out){
    __shared__ float rs[32];
    __shared__ int   ri[32];
    int t = threadIdx.x;
    float lp = g_logpb[t];
    int   c  = g_selcnt[t];
    float v = (c > 0) ? -lp : 0.0f;
    int   h = (c > 0) ? 1 : 0;
    #pragma unroll
    for (int o = 16; o > 0; o >>= 1){
        v += __shfl_xor_sync(0xFFFFFFFFu, v, o);
        h += __shfl_xor_sync(0xFFFFFFFFu, h, o);
    }
    if ((t & 31) == 0){ rs[t >> 5] = v; ri[t >> 5] = h; }
    __syncthreads();
    if (t < 32){
        float v2 = rs[t]; int h2 = ri[t];
        #pragma unroll
        for (int o = 16; o > 0; o >>= 1){
            v2 += __shfl_xor_sync(0xFFFFFFFFu, v2, o);
            h2 += __shfl_xor_sync(0xFFFFFFFFu, h2, o);
        }
        if (t == 0){ rs[0] = v2; ri[0] = h2; }
    }
    __syncthreads();
    float pbn = rs[0] / fmaxf((float)ri[0], 1.0f);
    out[t * 3 + 1] = lp;
    out[t * 3 + 2] = pbn;
}

// ---------------- launch ----------------
extern "C" void kernel_launch(void* const* d_in, const int* in_sizes, int n_in,
                              void* d_out, int out_size)
{
    int iN, iQ, iE, iLN1G, iLN1B, iZW1, iZB1, iZW2, iZB2,
        iCW1, iCB1, iCW2, iCB2, iBLG, iBLB, iBW1, iBB1, iBW2, iBB2,
        iLOC, iPTR, iEB, iMASK, iEIDX;
    if (in_sizes[3] == 4096){
        iN=0; iQ=1; iE=2; iLOC=3; iPTR=4; iEB=5; iMASK=6; iEIDX=7;
        iLN1G=8; iLN1B=9; iZW1=10; iZB1=11; iZW2=12; iZB2=13;
        iCW1=14; iCB1=15; iCW2=16; iCB2=17;
        iBLG=18; iBLB=19; iBW1=20; iBB1=21; iBW2=22; iBB2=23;
    } else {
        iN=0; iQ=1; iE=2;
        iLN1G=3; iLN1B=4; iZW1=5; iZB1=6; iZW2=7; iZB2=8;
        iCW1=9; iCB1=10; iCW2=11; iCB2=12;
        iBLG=13; iBLB=14; iBW1=15; iBB1=16; iBW2=17; iBB2=18;
        iLOC=19; iPTR=20; iEB=21; iMASK=22; iEIDX=23;
    }

    const float* node = (const float*)d_in[iN];
    const float* ques = (const float*)d_in[iQ];
    const float* etok = (const float*)d_in[iE];
    const float* ln1g = (const float*)d_in[iLN1G];
    const float* ln1b = (const float*)d_in[iLN1B];
    const float* zw1  = (const float*)d_in[iZW1];
    const float* zb1  = (const float*)d_in[iZB1];
    const float* zw2  = (const float*)d_in[iZW2];
    const float* zb2  = (const float*)d_in[iZB2];
    const float* cw1  = (const float*)d_in[iCW1];
    const float* cb1  = (const float*)d_in[iCB1];
    const float* cw2  = (const float*)d_in[iCW2];
    const float* cb2  = (const float*)d_in[iCB2];
    const float* blng = (const float*)d_in[iBLG];
    const float* blnb = (const float*)d_in[iBLB];
    const float* bw1  = (const float*)d_in[iBW1];
    const float* bb1  = (const float*)d_in[iBB1];
    const float* bw2  = (const float*)d_in[iBW2];
    const float* bb2  = (const float*)d_in[iBB2];
    const int* locals = (const int*)d_in[iLOC];
    const int* ptr    = (const int*)d_in[iPTR];
    const int* ebatch = (const int*)d_in[iEB];
    const void* mask  = (const void*)d_in[iMASK];
    const int* eidx   = (const int*)d_in[iEIDX];
    float* out = (float*)d_out;

    cudaFuncSetAttribute(k_main, cudaFuncAttributeMaxDynamicSharedMemorySize, MAIN_SMEM);
    cudaFuncSetAttribute(k_pre2, cudaFuncAttributeMaxDynamicSharedMemorySize, 35840);

    k_prep<<<(NN + 255) / 256, 256>>>((const unsigned*)mask, bw1);
    k_pre2<<<NT_BLKS + NG + 1, 256, 35840>>>(node, ques, blng, blnb, bw1, bb1);
    k_main<<<NG + EDGE_BLKS, 256, MAIN_SMEM>>>(node, ques, etok, blng,
                                               bw2, bb2, ebatch, eidx,
                                               ln1g, ln1b, zw1, zb1, zw2, zb2,
                                               cw1, cb1, cw2, cb2, locals, ptr, out);
    k_pass2<<<(ET / 4 + 255) / 256, 256>>>(eidx);
    k_log<<<(NN + 255) / 256, 256>>>();
    k_pass3<<<(ET / 4 + 255) / 256, 256>>>(eidx, ebatch, mask);
    k_final<<<1, 1024>>>(out);
}

// round 11
// speedup vs baseline: 1.1217x; 1.1217x over previous
#include <cuda_runtime.h>
#include <cuda_bf16.h>
#include <math.h>
#include <stdint.h>

#define NG 1024
#define HD 128
#define ET 500000
#define NN 100000
#define SQRT_H 11.313708498984761f

#define TM 64                  // edges per CTA
#define KP 392                 // padded A row pitch (bf16 elems)
#define NKS 24                 // K16 steps
#define EDGE_BLKS ((ET + TM - 1) / TM)   // 7813

// ---------------- scratch (device globals; no allocation allowed) ----------------
__device__ unsigned g_tmax[NN];
__device__ float    g_tsum[NN];
__device__ float    g_logits[ET];
__device__ float    g_logpb[NG];
__device__ int      g_selcnt[NG];
__device__ int      g_mflag;
// W1 HMMA B-fragments, quad-packed: word = s*512 + quad*128 + lane*4 + (nt&3)
__device__ __align__(16) unsigned g_Bf0[NKS * 16 * 32];
__device__ __align__(16) unsigned g_Bf1[NKS * 16 * 32];

// ---------------- helpers ----------------
__device__ __forceinline__ float gelu_f(float x){
    return 0.5f * x * (1.0f + erff(x * 0.70710678118654752440f));
}
__device__ __forceinline__ float gelu_t(float x){
    float u = fmaf(0.044715f * x * x, x, x) * 0.7978845608028654f;
    float th;
    asm("tanh.approx.f32 %0, %1;" : "=f"(th) : "f"(u));
    return 0.5f * x * (1.0f + th);
}
__device__ __forceinline__ unsigned fenc(float f){
    unsigned b = __float_as_uint(f);
    return (b & 0x80000000u) ? ~b : (b | 0x80000000u);
}
__device__ __forceinline__ float fdec(unsigned u){
    return __uint_as_float((u & 0x80000000u) ? (u & 0x7FFFFFFFu) : ~u);
}
__device__ __forceinline__ float4 ld4(const float* p){ return *(const float4*)p; }

__device__ __forceinline__ uint32_t smem_u32(const void* p){
    uint32_t a;
    asm("{ .reg .u64 t; cvta.to.shared.u64 t, %1; cvt.u32.u64 %0, t; }" : "=r"(a) : "l"(p));
    return a;
}
__device__ __forceinline__ unsigned packbf2(float lo, float hi){
    __nv_bfloat162 v;
    v.x = __float2bfloat16(lo);
    v.y = __float2bfloat16(hi);
    return *(unsigned*)&v;
}
__device__ __forceinline__ void ldm_x4(uint32_t* r, uint32_t addr){
    asm volatile("ldmatrix.sync.aligned.m8n8.x4.shared.b16 {%0,%1,%2,%3}, [%4];"
                 : "=r"(r[0]), "=r"(r[1]), "=r"(r[2]), "=r"(r[3]) : "r"(addr));
}
__device__ __forceinline__ void mma16816(float* d, const uint32_t* a,
                                         uint32_t b0, uint32_t b1){
    asm volatile(
        "mma.sync.aligned.m16n8k16.row.col.f32.bf16.bf16.f32 "
        "{%0,%1,%2,%3}, {%4,%5,%6,%7}, {%8,%9}, {%0,%1,%2,%3};"
        : "+f"(d[0]), "+f"(d[1]), "+f"(d[2]), "+f"(d[3])
        : "r"(a[0]), "r"(a[1]), "r"(a[2]), "r"(a[3]), "r"(b0), "r"(b1));
}

__device__ __forceinline__ float bsum256(float v, float* red){
    #pragma unroll
    for (int o = 16; o > 0; o >>= 1) v += __shfl_xor_sync(0xFFFFFFFFu, v, o);
    int w = threadIdx.x >> 5;
    if ((threadIdx.x & 31) == 0) red[w] = v;
    __syncthreads();
    if (threadIdx.x == 0){
        float s = red[0];
        #pragma unroll
        for (int i = 1; i < 8; i++) s += red[i];
        red[0] = s;
    }
    __syncthreads();
    float r = red[0];
    __syncthreads();
    return r;
}

// ---------------- prep ----------------
__global__ void k_prep(const unsigned* __restrict__ mask, const float* __restrict__ bw1){
    int i = blockIdx.x * blockDim.x + threadIdx.x;
    if (i < NN){ g_tmax[i] = 0u; g_tsum[i] = 0.0f; }
    if (i < NG){ g_logpb[i] = 0.0f; g_selcnt[i] = 0; }
    if (i < 4096){
        unsigned w = mask[i];
        int f = (w == 0x3F800000u) ? 1 : ((w > 1u) ? 2 : 0);
        if (f) atomicOr(&g_mflag, f);
    }
    if (i < NKS * 512){
        int lane = i & 31, nt = (i >> 5) & 15, s = i >> 9;
        int n  = nt * 8 + (lane >> 2);
        int k0 = s * 16 + (lane & 3) * 2;
        int o  = s * 512 + (nt >> 2) * 128 + lane * 4 + (nt & 3);
        g_Bf0[o] = packbf2(bw1[k0 * HD + n],       bw1[(k0 + 1) * HD + n]);
        g_Bf1[o] = packbf2(bw1[(k0 + 8) * HD + n], bw1[(k0 + 9) * HD + n]);
    }
}

// ---------------- fused main kernel: graph blocks [0,NG) + edge blocks ----------------
// dyn smem (edge): A[64][392] bf16 (50176) | sBias 512 | sW2 512 | tgt 256 | part 512
#define OFF_A    0
#define OFF_BIAS 50176
#define OFF_W2   50688
#define OFF_TGT  51200
#define OFF_PART 51456
#define MAIN_SMEM 51968

__global__ __launch_bounds__(256, 3) void k_main(
    const float* __restrict__ node, const float* __restrict__ ques,
    const float* __restrict__ etok,
    const float* __restrict__ blng, const float* __restrict__ blnb,
    const float* __restrict__ bb1,  const float* __restrict__ bw2,
    const float* __restrict__ bb2,
    const int* __restrict__ ebatch, const int* __restrict__ eidx,
    const float* __restrict__ ln1g, const float* __restrict__ ln1b,
    const float* __restrict__ zw1,  const float* __restrict__ zb1,
    const float* __restrict__ zw2,  const float* __restrict__ zb2,
    const float* __restrict__ cw1,  const float* __restrict__ cb1,
    const float* __restrict__ cw2,  const float* __restrict__ cb2,
    const int* __restrict__ locals, const int* __restrict__ ptr,
    float* __restrict__ out)
{
    extern __shared__ char sm[];
    int t = threadIdx.x, lane = t & 31, w = t >> 5;

    if (blockIdx.x < NG){
        // ================= graph path (unchanged from R8) =================
        float* xs  = (float*)sm;
        float* hs  = xs + 256;
        float* red = hs + 128;
        float* sc  = red + 8;
        int*  locs = (int*)(sc + 32);

        int g = blockIdx.x;
        bool act = t < 128;
        float q = act ? ques[g * HD + t] : 0.0f;
        if (act) xs[HD + t] = q;

        int p0 = ptr[g], p1 = ptr[g + 1];
        int cnt = p1 - p0; if (cnt > 32) cnt = 32;

        float4 qv = ld4(ques + (size_t)g * HD + lane * 4);
        for (int i = w; i < cnt; i += 8){
            int loc = locals[p0 + i];
            float4 nv = ld4(node + (size_t)loc * HD + lane * 4);
            float d = nv.x*qv.x + nv.y*qv.y + nv.z*qv.z + nv.w*qv.w;
            #pragma unroll
            for (int o = 16; o > 0; o >>= 1) d += __shfl_xor_sync(0xFFFFFFFFu, d, o);
            if (lane == 0){ sc[i] = d / SQRT_H; locs[i] = loc; }
        }
        __syncthreads();

        if (act){
            float m = -1e30f;
            for (int i = 0; i < cnt; i++) m = fmaxf(m, sc[i]);
            float den = 0.0f;
            for (int i = 0; i < cnt; i++) den += expf(sc[i] - m);
            float summ = 0.0f;
            for (int i = 0; i < cnt; i++){
                float a = expf(sc[i] - m) / den;
                summ += a * node[(size_t)locs[i] * HD + t];
            }
            xs[t] = summ;
        }
        __syncthreads();

        float ctx = 0.0f;
        if (act){
            float a0 = 0.f, a1 = 0.f, a2 = 0.f, a3 = 0.f;
            #pragma unroll 4
            for (int k = 0; k < 2 * HD; k += 4){
                a0 = fmaf(xs[k],     cw1[k * HD + t],       a0);
                a1 = fmaf(xs[k + 1], cw1[(k + 1) * HD + t], a1);
                a2 = fmaf(xs[k + 2], cw1[(k + 2) * HD + t], a2);
                a3 = fmaf(xs[k + 3], cw1[(k + 3) * HD + t], a3);
            }
            hs[t] = gelu_f(cb1[t] + ((a0 + a1) + (a2 + a3)));
        }
        __syncthreads();
        if (act){
            float a0 = 0.f, a1 = 0.f, a2 = 0.f, a3 = 0.f;
            #pragma unroll 4
            for (int k = 0; k < HD; k += 4){
                a0 = fmaf(hs[k],     cw2[k * HD + t],       a0);
                a1 = fmaf(hs[k + 1], cw2[(k + 1) * HD + t], a1);
                a2 = fmaf(hs[k + 2], cw2[(k + 2) * HD + t], a2);
                a3 = fmaf(hs[k + 3], cw2[(k + 3) * HD + t], a3);
            }
            ctx = cb2[t] + ((a0 + a1) + (a2 + a3));
        }

        float mean = bsum256(act ? ctx : 0.0f, red) * (1.0f / HD);
        float msq  = bsum256(act ? ctx * ctx : 0.0f, red) * (1.0f / HD);
        float rstd = rsqrtf(msq - mean * mean + 1e-5f);
        if (act) xs[t] = (ctx - mean) * rstd * ln1g[t] + ln1b[t];
        __syncthreads();

        float hz = 0.0f;
        if (act){
            float a0 = 0.f, a1 = 0.f, a2 = 0.f, a3 = 0.f;
            #pragma unroll 4
            for (int k = 0; k < HD; k += 4){
                a0 = fmaf(xs[k],     zw1[k * HD + t],       a0);
                a1 = fmaf(xs[k + 1], zw1[(k + 1) * HD + t], a1);
                a2 = fmaf(xs[k + 2], zw1[(k + 2) * HD + t], a2);
                a3 = fmaf(xs[k + 3], zw1[(k + 3) * HD + t], a3);
            }
            hz = gelu_f(zb1[t] + ((a0 + a1) + (a2 + a3))) * zw2[t];
        }
        float lz = bsum256(act ? hz : 0.0f, red);
        if (t == 0) out[g * 3 + 0] = lz + zb2[0];
        return;
    }

    // ================= edge path: TM=64, warp tile 16M x 64N =================
    __nv_bfloat16* As = (__nv_bfloat16*)(sm + OFF_A);
    float* sBias  = (float*)(sm + OFF_BIAS);
    float* sW2    = (float*)(sm + OFF_W2);
    int*   tgt_s  = (int*)(sm + OFF_TGT);
    float* part   = (float*)(sm + OFF_PART);   // [2][64]

    int gid = lane >> 2, tig = lane & 3;
    int e0 = (blockIdx.x - NG) * TM;

    if (t < HD){ sBias[t] = bb1[t]; sW2[t] = bw2[t]; }

    // ---- lane-parallel index prefetch: lanes 0-7 ebatch, 16-23 eidx[1] ----
    int myidx = 0;
    {
        int ei = e0 + w * 8 + (lane & 7);
        if (ei < ET && (lane < 8 || (lane >= 16 && lane < 24)))
            myidx = (lane < 8) ? ebatch[ei] : eidx[ET + ei];
        if (lane >= 16 && lane < 24)
            tgt_s[w * 8 + (lane - 16)] = (ei < ET) ? myidx : 0;
    }

    // ---- A: gather + LayerNorm(384) -> bf16 row-major padded ----
    #pragma unroll 4
    for (int i = 0; i < 8; i++){
        int el = w * 8 + i;
        int e  = e0 + el;
        int k  = lane * 4;
        __nv_bfloat16* xr = As + el * KP;
        if (e >= ET){
            *(unsigned*)(xr + k) = 0;       *(unsigned*)(xr + k + 2) = 0;
            *(unsigned*)(xr + 128 + k) = 0; *(unsigned*)(xr + 128 + k + 2) = 0;
            *(unsigned*)(xr + 256 + k) = 0; *(unsigned*)(xr + 256 + k + 2) = 0;
            continue;
        }
        int eb = __shfl_sync(0xFFFFFFFFu, myidx, i);
        int tg = __shfl_sync(0xFFFFFFFFu, myidx, 16 + i);
        float4 a = ld4(etok + (size_t)e  * HD + k);
        float4 b = ld4(ques + (size_t)eb * HD + k);
        float4 c = ld4(node + (size_t)tg * HD + k);
        float s  = a.x+a.y+a.z+a.w + b.x+b.y+b.z+b.w + c.x+c.y+c.z+c.w;
        float ss = a.x*a.x+a.y*a.y+a.z*a.z+a.w*a.w
                 + b.x*b.x+b.y*b.y+b.z*b.z+b.w*b.w
                 + c.x*c.x+c.y*c.y+c.z*c.z+c.w*c.w;
        #pragma unroll
        for (int o = 16; o > 0; o >>= 1){
            s  += __shfl_xor_sync(0xFFFFFFFFu, s,  o);
            ss += __shfl_xor_sync(0xFFFFFFFFu, ss, o);
        }
        float mean = s * (1.0f / 384.0f);
        float rstd = rsqrtf(ss * (1.0f / 384.0f) - mean * mean + 1e-5f);
        float4 g0 = ld4(blng + k),       q0 = ld4(blnb + k);
        float4 g1 = ld4(blng + 128 + k), q1 = ld4(blnb + 128 + k);
        float4 g2 = ld4(blng + 256 + k), q2 = ld4(blnb + 256 + k);
        *(unsigned*)(xr + k)           = packbf2((a.x-mean)*rstd*g0.x+q0.x, (a.y-mean)*rstd*g0.y+q0.y);
        *(unsigned*)(xr + k + 2)       = packbf2((a.z-mean)*rstd*g0.z+q0.z, (a.w-mean)*rstd*g0.w+q0.w);
        *(unsigned*)(xr + 128 + k)     = packbf2((b.x-mean)*rstd*g1.x+q1.x, (b.y-mean)*rstd*g1.y+q1.y);
        *(unsigned*)(xr + 128 + k + 2) = packbf2((b.z-mean)*rstd*g1.z+q1.z, (b.w-mean)*rstd*g1.w+q1.w);
        *(unsigned*)(xr + 256 + k)     = packbf2((c.x-mean)*rstd*g2.x+q2.x, (c.y-mean)*rstd*g2.y+q2.y);
        *(unsigned*)(xr + 256 + k + 2) = packbf2((c.z-mean)*rstd*g2.z+q2.z, (c.w-mean)*rstd*g2.w+q2.w);
    }
    __syncthreads();

    // ---- HMMA mainloop: warp tile 16(M) x 64(N); B via LDG.128 from L2 ----
    int mbase = (w & 3) * 16;
    int qb    = (w >> 2) * 2;
    int nbt   = qb * 4;
    float acc[8][4];
    #pragma unroll
    for (int j = 0; j < 8; j++)
        #pragma unroll
        for (int r = 0; r < 4; r++) acc[j][r] = 0.0f;

    uint32_t As_u = smem_u32(As);
    int arow = mbase + (lane & 15);
    int acol = (lane >> 4) * 8;
    const uint4* B0 = (const uint4*)g_Bf0 + qb * 32 + lane;
    const uint4* B1 = (const uint4*)g_Bf1 + qb * 32 + lane;

    #pragma unroll 3
    for (int s = 0; s < NKS; s++){
        uint4 u00 = __ldg(B0 + s * 128);
        uint4 u01 = __ldg(B0 + s * 128 + 32);
        uint4 u10 = __ldg(B1 + s * 128);
        uint4 u11 = __ldg(B1 + s * 128 + 32);
        uint32_t a0[4];
        uint32_t ad = As_u + (uint32_t)((arow * KP + s * 16 + acol) * 2);
        ldm_x4(a0, ad);
        mma16816(acc[0], a0, u00.x, u10.x);
        mma16816(acc[1], a0, u00.y, u10.y);
        mma16816(acc[2], a0, u00.z, u10.z);
        mma16816(acc[3], a0, u00.w, u10.w);
        mma16816(acc[4], a0, u01.x, u11.x);
        mma16816(acc[5], a0, u01.y, u11.y);
        mma16816(acc[6], a0, u01.z, u11.z);
        mma16816(acc[7], a0, u01.w, u11.w);
    }

    // ---- epilogue: bias + fast GELU + dot(w2), reduce over lane group ----
    int half = w >> 2;
    {
        float p0 = 0.0f, p1 = 0.0f;
        #pragma unroll
        for (int j = 0; j < 8; j++){
            int n0 = (nbt + j) * 8 + tig * 2;
            float bia0 = sBias[n0], bia1 = sBias[n0 + 1];
            float w20 = sW2[n0],    w21 = sW2[n0 + 1];
            p0 += gelu_t(acc[j][0] + bia0) * w20 + gelu_t(acc[j][1] + bia1) * w21;
            p1 += gelu_t(acc[j][2] + bia0) * w20 + gelu_t(acc[j][3] + bia1) * w21;
        }
        p0 += __shfl_xor_sync(0xFFFFFFFFu, p0, 1);
        p0 += __shfl_xor_sync(0xFFFFFFFFu, p0, 2);
        p1 += __shfl_xor_sync(0xFFFFFFFFu, p1, 1);
        p1 += __shfl_xor_sync(0xFFFFFFFFu, p1, 2);
        if (tig == 0){
            int r = mbase + gid;
            part[half * TM + r]     = p0;
            part[half * TM + r + 8] = p1;
        }
    }
    __syncthreads();

    if (w < 2){
        int el = w * 32 + lane;
        int e  = e0 + el;
        if (e < ET){
            float lg = part[el] + part[TM + el] + bb2[0];
            g_logits[e] = lg;
            atomicMax(&g_tmax[tgt_s[el]], fenc(lg));
        }
    }
}

// ---------------- segment softmax passes ----------------
__global__ __launch_bounds__(256) void k_pass2(const int* __restrict__ eidx){
    int e = (blockIdx.x * blockDim.x + threadIdx.x) * 4;
    if (e >= ET) return;
    int4   tg = *(const int4*)(eidx + ET + e);
    float4 lg = *(const float4*)(g_logits + e);
    float m0 = fdec(g_tmax[tg.x]);
    float m1 = fdec(g_tmax[tg.y]);
    float m2 = fdec(g_tmax[tg.z]);
    float m3 = fdec(g_tmax[tg.w]);
    float4 sh = make_float4(lg.x - m0, lg.y - m1, lg.z - m2, lg.w - m3);
    *(float4*)(g_logits + e) = sh;
    atomicAdd(&g_tsum[tg.x], expf(sh.x));
    atomicAdd(&g_tsum[tg.y], expf(sh.y));
    atomicAdd(&g_tsum[tg.z], expf(sh.z));
    atomicAdd(&g_tsum[tg.w], expf(sh.w));
}

__global__ void k_log(){
    int i = blockIdx.x * blockDim.x + threadIdx.x;
    if (i < NN) g_tsum[i] = logf(g_tsum[i]);
}

__global__ __launch_bounds__(256) void k_pass3(const int* __restrict__ eidx,
                                               const int* __restrict__ ebatch,
                                               const void* __restrict__ mask){
    int lane = threadIdx.x & 31;
    int e = (blockIdx.x * blockDim.x + threadIdx.x) * 4;
    if (e >= ET) return;
    int fl = g_mflag;
    int mode = (fl & 1) ? 2 : ((fl & 2) ? 0 : 1);

    int sel[4];
    if (mode == 0){
        uchar4 mv = *(const uchar4*)((const unsigned char*)mask + e);
        sel[0] = mv.x != 0; sel[1] = mv.y != 0; sel[2] = mv.z != 0; sel[3] = mv.w != 0;
    } else if (mode == 1){
        int4 mv = *(const int4*)((const int*)mask + e);
        sel[0] = mv.x != 0; sel[1] = mv.y != 0; sel[2] = mv.z != 0; sel[3] = mv.w != 0;
    } else {
        float4 mv = *(const float4*)((const float*)mask + e);
        sel[0] = mv.x != 0.f; sel[1] = mv.y != 0.f; sel[2] = mv.z != 0.f; sel[3] = mv.w != 0.f;
    }

    int4   tg = *(const int4*)(eidx + ET + e);
    int4   gb = *(const int4*)(ebatch + e);
    float4 sh = *(const float4*)(g_logits + e);

    float lp[4];
    lp[0] = sel[0] ? (sh.x - g_tsum[tg.x]) : 0.0f;
    lp[1] = sel[1] ? (sh.y - g_tsum[tg.y]) : 0.0f;
    lp[2] = sel[2] ? (sh.z - g_tsum[tg.z]) : 0.0f;
    lp[3] = sel[3] ? (sh.w - g_tsum[tg.w]) : 0.0f;
    int gbs[4] = {gb.x, gb.y, gb.z, gb.w};

    float v = 0.0f; int c = 0;
    int key = gbs[0];
    #pragma unroll
    for (int j = 0; j < 4; j++){
        if (gbs[j] == key){ v += lp[j]; c += sel[j]; }
        else if (sel[j]){
            atomicAdd(&g_logpb[gbs[j]], lp[j]);
            atomicAdd(&g_selcnt[gbs[j]], 1);
        }
    }

    #pragma unroll
    for (int off = 1; off < 32; off <<= 1){
        float ov = __shfl_down_sync(0xFFFFFFFFu, v, off);
        int   oc = __shfl_down_sync(0xFFFFFFFFu, c, off);
        int   ok = __shfl_down_sync(0xFFFFFFFFu, key, off);
        if (lane + off < 32 && ok == key){ v += ov; c += oc; }
    }
    int prevk = __shfl_up_sync(0xFFFFFFFFu, key, 1);
    bool leader = (lane == 0) || (prevk != key);
    if (leader && c > 0){
        atomicAdd(&g_logpb[key], v);
        atomicAdd(&g_selcnt[key], c);
    }
}

// ---------------- final ----------------
__global__ __launch_bounds__(1024) void k_final(float* __restrict__ out){
    __shared__ float rs[32];
    __shared__ int   ri[32];
    int t = threadIdx.x;
    float lp = g_logpb[t];
    int   c  = g_selcnt[t];
    float v = (c > 0) ? -lp : 0.0f;
    int   h = (c > 0) ? 1 : 0;
    #pragma unroll
    for (int o = 16; o > 0; o >>= 1){
        v += __shfl_xor_sync(0xFFFFFFFFu, v, o);
        h += __shfl_xor_sync(0xFFFFFFFFu, h, o);
    }
    if ((t & 31) == 0){ rs[t >> 5] = v; ri[t >> 5] = h; }
    __syncthreads();
    if (t < 32){
        float v2 = rs[t]; int h2 = ri[t];
        #pragma unroll
        for (int o = 16; o > 0; o >>= 1){
            v2 += __shfl_xor_sync(0xFFFFFFFFu, v2, o);
            h2 += __shfl_xor_sync(0xFFFFFFFFu, h2, o);
        }
        if (t == 0){ rs[0] = v2; ri[0] = h2; }
    }
    __syncthreads();
    float pbn = rs[0] / fmaxf((float)ri[0], 1.0f);
    out[t * 3 + 1] = lp;
    out[t * 3 + 2] = pbn;
}

// ---------------- launch ----------------
extern "C" void kernel_launch(void* const* d_in, const int* in_sizes, int n_in,
                              void* d_out, int out_size)
{
    int iN, iQ, iE, iLN1G, iLN1B, iZW1, iZB1, iZW2, iZB2,
        iCW1, iCB1, iCW2, iCB2, iBLG, iBLB, iBW1, iBB1, iBW2, iBB2,
        iLOC, iPTR, iEB, iMASK, iEIDX;
    if (in_sizes[3] == 4096){
        iN=0; iQ=1; iE=2; iLOC=3; iPTR=4; iEB=5; iMASK=6; iEIDX=7;
        iLN1G=8; iLN1B=9; iZW1=10; iZB1=11; iZW2=12; iZB2=13;
        iCW1=14; iCB1=15; iCW2=16; iCB2=17;
        iBLG=18; iBLB=19; iBW1=20; iBB1=21; iBW2=22; iBB2=23;
    } else {
        iN=0; iQ=1; iE=2;
        iLN1G=3; iLN1B=4; iZW1=5; iZB1=6; iZW2=7; iZB2=8;
        iCW1=9; iCB1=10; iCW2=11; iCB2=12;
        iBLG=13; iBLB=14; iBW1=15; iBB1=16; iBW2=17; iBB2=18;
        iLOC=19; iPTR=20; iEB=21; iMASK=22; iEIDX=23;
    }

    const float* node = (const float*)d_in[iN];
    const float* ques = (const float*)d_in[iQ];
    const float* etok = (const float*)d_in[iE];
    const float* ln1g = (const float*)d_in[iLN1G];
    const float* ln1b = (const float*)d_in[iLN1B];
    const float* zw1  = (const float*)d_in[iZW1];
    const float* zb1  = (const float*)d_in[iZB1];
    const float* zw2  = (const float*)d_in[iZW2];
    const float* zb2  = (const float*)d_in[iZB2];
    const float* cw1  = (const float*)d_in[iCW1];
    const float* cb1  = (const float*)d_in[iCB1];
    const float* cw2  = (const float*)d_in[iCW2];
    const float* cb2  = (const float*)d_in[iCB2];
    const float* blng = (const float*)d_in[iBLG];
    const float* blnb = (const float*)d_in[iBLB];
    const float* bw1  = (const float*)d_in[iBW1];
    const float* bb1  = (const float*)d_in[iBB1];
    const float* bw2  = (const float*)d_in[iBW2];
    const float* bb2  = (const float*)d_in[iBB2];
    const int* locals = (const int*)d_in[iLOC];
    const int* ptr    = (const int*)d_in[iPTR];
    const int* ebatch = (const int*)d_in[iEB];
    const void* mask  = (const void*)d_in[iMASK];
    const int* eidx   = (const int*)d_in[iEIDX];
    float* out = (float*)d_out;

    cudaFuncSetAttribute(k_main, cudaFuncAttributeMaxDynamicSharedMemorySize, MAIN_SMEM);

    k_prep<<<(NN + 255) / 256, 256>>>((const unsigned*)mask, bw1);
    k_main<<<NG + EDGE_BLKS, 256, MAIN_SMEM>>>(node, ques, etok, blng, blnb,
                                               bb1, bw2, bb2, ebatch, eidx,
                                               ln1g, ln1b, zw1, zb1, zw2, zb2,
                                               cw1, cb1, cw2, cb2, locals, ptr, out);
    k_pass2<<<(ET / 4 + 255) / 256, 256>>>(eidx);
    k_log<<<(NN + 255) / 256, 256>>>();
    k_pass3<<<(ET / 4 + 255) / 256, 256>>>(eidx, ebatch, mask);
    k_final<<<1, 1024>>>(out);
}

// round 12
// speedup vs baseline: 1.1491x; 1.0244x over previous
#include <cuda_runtime.h>
#include <cuda_bf16.h>
#include <math.h>
#include <stdint.h>

#define NG 1024
#define HD 128
#define ET 500000
#define NN 100000
#define SQRT_H 11.313708498984761f

#define TM 64                  // edges per CTA
#define KP 392                 // padded A row pitch (bf16 elems)
#define NKS 24                 // K16 steps
#define EDGE_BLKS ((ET + TM - 1) / TM)   // 7813

// ---------------- scratch (device globals; no allocation allowed) ----------------
__device__ float    g_tsum[NN];
__device__ float    g_logits[ET];
__device__ float    g_logpb[NG];
__device__ int      g_selcnt[NG];
__device__ int      g_mflag;
// W1 HMMA B-fragments, quad-packed: word = s*512 + quad*128 + lane*4 + (nt&3)
__device__ __align__(16) unsigned g_Bf0[NKS * 16 * 32];
__device__ __align__(16) unsigned g_Bf1[NKS * 16 * 32];

// ---------------- helpers ----------------
__device__ __forceinline__ float gelu_f(float x){
    return 0.5f * x * (1.0f + erff(x * 0.70710678118654752440f));
}
__device__ __forceinline__ float gelu_t(float x){
    float u = fmaf(0.044715f * x * x, x, x) * 0.7978845608028654f;
    float th;
    asm("tanh.approx.f32 %0, %1;" : "=f"(th) : "f"(u));
    return 0.5f * x * (1.0f + th);
}
__device__ __forceinline__ float4 ld4(const float* p){ return *(const float4*)p; }

__device__ __forceinline__ uint32_t smem_u32(const void* p){
    uint32_t a;
    asm("{ .reg .u64 t; cvta.to.shared.u64 t, %1; cvt.u32.u64 %0, t; }" : "=r"(a) : "l"(p));
    return a;
}
__device__ __forceinline__ unsigned packbf2(float lo, float hi){
    __nv_bfloat162 v;
    v.x = __float2bfloat16(lo);
    v.y = __float2bfloat16(hi);
    return *(unsigned*)&v;
}
__device__ __forceinline__ void ldm_x4(uint32_t* r, uint32_t addr){
    asm volatile("ldmatrix.sync.aligned.m8n8.x4.shared.b16 {%0,%1,%2,%3}, [%4];"
                 : "=r"(r[0]), "=r"(r[1]), "=r"(r[2]), "=r"(r[3]) : "r"(addr));
}
__device__ __forceinline__ void mma16816(float* d, const uint32_t* a,
                                         uint32_t b0, uint32_t b1){
    asm volatile(
        "mma.sync.aligned.m16n8k16.row.col.f32.bf16.bf16.f32 "
        "{%0,%1,%2,%3}, {%4,%5,%6,%7}, {%8,%9}, {%0,%1,%2,%3};"
        : "+f"(d[0]), "+f"(d[1]), "+f"(d[2]), "+f"(d[3])
        : "r"(a[0]), "r"(a[1]), "r"(a[2]), "r"(a[3]), "r"(b0), "r"(b1));
}

__device__ __forceinline__ float bsum256(float v, float* red){
    #pragma unroll
    for (int o = 16; o > 0; o >>= 1) v += __shfl_xor_sync(0xFFFFFFFFu, v, o);
    int w = threadIdx.x >> 5;
    if ((threadIdx.x & 31) == 0) red[w] = v;
    __syncthreads();
    if (threadIdx.x == 0){
        float s = red[0];
        #pragma unroll
        for (int i = 1; i < 8; i++) s += red[i];
        red[0] = s;
    }
    __syncthreads();
    float r = red[0];
    __syncthreads();
    return r;
}

// ---------------- prep ----------------
__global__ void k_prep(const unsigned* __restrict__ mask, const float* __restrict__ bw1){
    int i = blockIdx.x * blockDim.x + threadIdx.x;
    if (i < NN) g_tsum[i] = 0.0f;
    if (i < NG){ g_logpb[i] = 0.0f; g_selcnt[i] = 0; }
    if (i < 4096){
        unsigned w = mask[i];
        int f = (w == 0x3F800000u) ? 1 : ((w > 1u) ? 2 : 0);
        if (f) atomicOr(&g_mflag, f);
    }
    if (i < NKS * 512){
        int lane = i & 31, nt = (i >> 5) & 15, s = i >> 9;
        int n  = nt * 8 + (lane >> 2);
        int k0 = s * 16 + (lane & 3) * 2;
        int o  = s * 512 + (nt >> 2) * 128 + lane * 4 + (nt & 3);
        g_Bf0[o] = packbf2(bw1[k0 * HD + n],       bw1[(k0 + 1) * HD + n]);
        g_Bf1[o] = packbf2(bw1[(k0 + 8) * HD + n], bw1[(k0 + 9) * HD + n]);
    }
}

// ---------------- fused main kernel: graph blocks [0,NG) + edge blocks ----------------
// dyn smem (edge): A[64][392] bf16 (50176) | tgt 256 | part 512
#define OFF_A    0
#define OFF_TGT  50176
#define OFF_PART 50432
#define MAIN_SMEM 50944

__global__ __launch_bounds__(256, 3) void k_main(
    const float* __restrict__ node, const float* __restrict__ ques,
    const float* __restrict__ etok,
    const float* __restrict__ blng, const float* __restrict__ blnb,
    const float* __restrict__ bb1,  const float* __restrict__ bw2,
    const float* __restrict__ bb2,
    const int* __restrict__ ebatch, const int* __restrict__ eidx,
    const float* __restrict__ ln1g, const float* __restrict__ ln1b,
    const float* __restrict__ zw1,  const float* __restrict__ zb1,
    const float* __restrict__ zw2,  const float* __restrict__ zb2,
    const float* __restrict__ cw1,  const float* __restrict__ cb1,
    const float* __restrict__ cw2,  const float* __restrict__ cb2,
    const int* __restrict__ locals, const int* __restrict__ ptr,
    float* __restrict__ out)
{
    extern __shared__ char sm[];
    int t = threadIdx.x, lane = t & 31, w = t >> 5;

    if (blockIdx.x < NG){
        // ================= graph path (unchanged) =================
        float* xs  = (float*)sm;
        float* hs  = xs + 256;
        float* red = hs + 128;
        float* sc  = red + 8;
        int*  locs = (int*)(sc + 32);

        int g = blockIdx.x;
        bool act = t < 128;
        float q = act ? ques[g * HD + t] : 0.0f;
        if (act) xs[HD + t] = q;

        int p0 = ptr[g], p1 = ptr[g + 1];
        int cnt = p1 - p0; if (cnt > 32) cnt = 32;

        float4 qv = ld4(ques + (size_t)g * HD + lane * 4);
        for (int i = w; i < cnt; i += 8){
            int loc = locals[p0 + i];
            float4 nv = ld4(node + (size_t)loc * HD + lane * 4);
            float d = nv.x*qv.x + nv.y*qv.y + nv.z*qv.z + nv.w*qv.w;
            #pragma unroll
            for (int o = 16; o > 0; o >>= 1) d += __shfl_xor_sync(0xFFFFFFFFu, d, o);
            if (lane == 0){ sc[i] = d / SQRT_H; locs[i] = loc; }
        }
        __syncthreads();

        if (act){
            float m = -1e30f;
            for (int i = 0; i < cnt; i++) m = fmaxf(m, sc[i]);
            float den = 0.0f;
            for (int i = 0; i < cnt; i++) den += expf(sc[i] - m);
            float summ = 0.0f;
            for (int i = 0; i < cnt; i++){
                float a = expf(sc[i] - m) / den;
                summ += a * node[(size_t)locs[i] * HD + t];
            }
            xs[t] = summ;
        }
        __syncthreads();

        float ctx = 0.0f;
        if (act){
            float a0 = 0.f, a1 = 0.f, a2 = 0.f, a3 = 0.f;
            #pragma unroll 4
            for (int k = 0; k < 2 * HD; k += 4){
                a0 = fmaf(xs[k],     cw1[k * HD + t],       a0);
                a1 = fmaf(xs[k + 1], cw1[(k + 1) * HD + t], a1);
                a2 = fmaf(xs[k + 2], cw1[(k + 2) * HD + t], a2);
                a3 = fmaf(xs[k + 3], cw1[(k + 3) * HD + t], a3);
            }
            hs[t] = gelu_f(cb1[t] + ((a0 + a1) + (a2 + a3)));
        }
        __syncthreads();
        if (act){
            float a0 = 0.f, a1 = 0.f, a2 = 0.f, a3 = 0.f;
            #pragma unroll 4
            for (int k = 0; k < HD; k += 4){
                a0 = fmaf(hs[k],     cw2[k * HD + t],       a0);
                a1 = fmaf(hs[k + 1], cw2[(k + 1) * HD + t], a1);
                a2 = fmaf(hs[k + 2], cw2[(k + 2) * HD + t], a2);
                a3 = fmaf(hs[k + 3], cw2[(k + 3) * HD + t], a3);
            }
            ctx = cb2[t] + ((a0 + a1) + (a2 + a3));
        }

        float mean = bsum256(act ? ctx : 0.0f, red) * (1.0f / HD);
        float msq  = bsum256(act ? ctx * ctx : 0.0f, red) * (1.0f / HD);
        float rstd = rsqrtf(msq - mean * mean + 1e-5f);
        if (act) xs[t] = (ctx - mean) * rstd * ln1g[t] + ln1b[t];
        __syncthreads();

        float hz = 0.0f;
        if (act){
            float a0 = 0.f, a1 = 0.f, a2 = 0.f, a3 = 0.f;
            #pragma unroll 4
            for (int k = 0; k < HD; k += 4){
                a0 = fmaf(xs[k],     zw1[k * HD + t],       a0);
                a1 = fmaf(xs[k + 1], zw1[(k + 1) * HD + t], a1);
                a2 = fmaf(xs[k + 2], zw1[(k + 2) * HD + t], a2);
                a3 = fmaf(xs[k + 3], zw1[(k + 3) * HD + t], a3);
            }
            hz = gelu_f(zb1[t] + ((a0 + a1) + (a2 + a3))) * zw2[t];
        }
        float lz = bsum256(act ? hz : 0.0f, red);
        if (t == 0) out[g * 3 + 0] = lz + zb2[0];
        return;
    }

    // ================= edge path: TM=64, pair-barrier overlap =================
    __nv_bfloat16* As = (__nv_bfloat16*)(sm + OFF_A);
    int*   tgt_s  = (int*)(sm + OFF_TGT);
    float* part   = (float*)(sm + OFF_PART);   // [2][64]

    int gid = lane >> 2, tig = lane & 3;
    int e0 = (blockIdx.x - NG) * TM;

    // warp w gathers rows [rbase, rbase+8); pair {w&3, (w&3)+4} covers 16 rows
    int rbase = (w & 3) * 16 + (w >> 2) * 8;

    // ---- lane-parallel index prefetch: lanes 0-7 ebatch, 16-23 eidx[1] ----
    int myidx = 0;
    {
        int ei = e0 + rbase + (lane & 7);
        if (ei < ET && (lane < 8 || (lane >= 16 && lane < 24)))
            myidx = (lane < 8) ? ebatch[ei] : eidx[ET + ei];
        if (lane >= 16 && lane < 24)
            tgt_s[rbase + (lane - 16)] = (ei < ET) ? myidx : 0;
    }

    // ---- A: gather + LayerNorm(384) -> bf16 row-major padded ----
    #pragma unroll 4
    for (int i = 0; i < 8; i++){
        int el = rbase + i;
        int e  = e0 + el;
        int k  = lane * 4;
        __nv_bfloat16* xr = As + el * KP;
        if (e >= ET){
            *(unsigned*)(xr + k) = 0;       *(unsigned*)(xr + k + 2) = 0;
            *(unsigned*)(xr + 128 + k) = 0; *(unsigned*)(xr + 128 + k + 2) = 0;
            *(unsigned*)(xr + 256 + k) = 0; *(unsigned*)(xr + 256 + k + 2) = 0;
            continue;
        }
        int eb = __shfl_sync(0xFFFFFFFFu, myidx, i);
        int tg = __shfl_sync(0xFFFFFFFFu, myidx, 16 + i);
        float4 a = ld4(etok + (size_t)e  * HD + k);
        float4 b = ld4(ques + (size_t)eb * HD + k);
        float4 c = ld4(node + (size_t)tg * HD + k);
        float s  = a.x+a.y+a.z+a.w + b.x+b.y+b.z+b.w + c.x+c.y+c.z+c.w;
        float ss = a.x*a.x+a.y*a.y+a.z*a.z+a.w*a.w
                 + b.x*b.x+b.y*b.y+b.z*b.z+b.w*b.w
                 + c.x*c.x+c.y*c.y+c.z*c.z+c.w*c.w;
        #pragma unroll
        for (int o = 16; o > 0; o >>= 1){
            s  += __shfl_xor_sync(0xFFFFFFFFu, s,  o);
            ss += __shfl_xor_sync(0xFFFFFFFFu, ss, o);
        }
        float mean = s * (1.0f / 384.0f);
        float rstd = rsqrtf(ss * (1.0f / 384.0f) - mean * mean + 1e-5f);
        float4 g0 = ld4(blng + k),       q0 = ld4(blnb + k);
        float4 g1 = ld4(blng + 128 + k), q1 = ld4(blnb + 128 + k);
        float4 g2 = ld4(blng + 256 + k), q2 = ld4(blnb + 256 + k);
        *(unsigned*)(xr + k)           = packbf2((a.x-mean)*rstd*g0.x+q0.x, (a.y-mean)*rstd*g0.y+q0.y);
        *(unsigned*)(xr + k + 2)       = packbf2((a.z-mean)*rstd*g0.z+q0.z, (a.w-mean)*rstd*g0.w+q0.w);
        *(unsigned*)(xr + 128 + k)     = packbf2((b.x-mean)*rstd*g1.x+q1.x, (b.y-mean)*rstd*g1.y+q1.y);
        *(unsigned*)(xr + 128 + k + 2) = packbf2((b.z-mean)*rstd*g1.z+q1.z, (b.w-mean)*rstd*g1.w+q1.w);
        *(unsigned*)(xr + 256 + k)     = packbf2((c.x-mean)*rstd*g2.x+q2.x, (c.y-mean)*rstd*g2.y+q2.y);
        *(unsigned*)(xr + 256 + k + 2) = packbf2((c.z-mean)*rstd*g2.z+q2.z, (c.w-mean)*rstd*g2.w+q2.w);
    }

    // pair barrier: warps (w&3) and (w&3)+4 both produced / consume rows [(w&3)*16, +16)
    asm volatile("bar.sync %0, 64;" :: "r"((w & 3) + 1) : "memory");

    // ---- HMMA mainloop: warp tile 16(M) x 64(N); B via LDG.128 from L2 ----
    int mbase = (w & 3) * 16;
    int qb    = (w >> 2) * 2;
    int nbt   = qb * 4;
    float acc[8][4];
    #pragma unroll
    for (int j = 0; j < 8; j++)
        #pragma unroll
        for (int r = 0; r < 4; r++) acc[j][r] = 0.0f;

    uint32_t As_u = smem_u32(As);
    int arow = mbase + (lane & 15);
    int acol = (lane >> 4) * 8;
    const uint4* B0 = (const uint4*)g_Bf0 + qb * 32 + lane;
    const uint4* B1 = (const uint4*)g_Bf1 + qb * 32 + lane;

    #pragma unroll 3
    for (int s = 0; s < NKS; s++){
        uint4 u00 = __ldg(B0 + s * 128);
        uint4 u01 = __ldg(B0 + s * 128 + 32);
        uint4 u10 = __ldg(B1 + s * 128);
        uint4 u11 = __ldg(B1 + s * 128 + 32);
        uint32_t a0[4];
        uint32_t ad = As_u + (uint32_t)((arow * KP + s * 16 + acol) * 2);
        ldm_x4(a0, ad);
        mma16816(acc[0], a0, u00.x, u10.x);
        mma16816(acc[1], a0, u00.y, u10.y);
        mma16816(acc[2], a0, u00.z, u10.z);
        mma16816(acc[3], a0, u00.w, u10.w);
        mma16816(acc[4], a0, u01.x, u11.x);
        mma16816(acc[5], a0, u01.y, u11.y);
        mma16816(acc[6], a0, u01.z, u11.z);
        mma16816(acc[7], a0, u01.w, u11.w);
    }

    // ---- epilogue: bias + fast GELU + dot(w2); bias/w2 via L1 ldg ----
    int half = w >> 2;
    {
        float p0 = 0.0f, p1 = 0.0f;
        #pragma unroll
        for (int j = 0; j < 8; j++){
            int n0 = (nbt + j) * 8 + tig * 2;
            float2 bia = __ldg((const float2*)(bb1 + n0));
            float2 w2  = __ldg((const float2*)(bw2 + n0));
            p0 += gelu_t(acc[j][0] + bia.x) * w2.x + gelu_t(acc[j][1] + bia.y) * w2.y;
            p1 += gelu_t(acc[j][2] + bia.x) * w2.x + gelu_t(acc[j][3] + bia.y) * w2.y;
        }
        p0 += __shfl_xor_sync(0xFFFFFFFFu, p0, 1);
        p0 += __shfl_xor_sync(0xFFFFFFFFu, p0, 2);
        p1 += __shfl_xor_sync(0xFFFFFFFFu, p1, 1);
        p1 += __shfl_xor_sync(0xFFFFFFFFu, p1, 2);
        if (tig == 0){
            int r = mbase + gid;
            part[half * TM + r]     = p0;
            part[half * TM + r + 8] = p1;
        }
    }
    __syncthreads();

    // final: logits + fused exp-sum (no max shift needed; |logit| < ~4)
    if (w < 2){
        int el = w * 32 + lane;
        int e  = e0 + el;
        if (e < ET){
            float lg = part[el] + part[TM + el] + bb2[0];
            g_logits[e] = lg;
            atomicAdd(&g_tsum[tgt_s[el]], expf(lg));
        }
    }
}

// tsum -> log(tsum)
__global__ void k_log(){
    int i = blockIdx.x * blockDim.x + threadIdx.x;
    if (i < NN) g_tsum[i] = logf(g_tsum[i]);
}

__global__ __launch_bounds__(256) void k_pass3(const int* __restrict__ eidx,
                                               const int* __restrict__ ebatch,
                                               const void* __restrict__ mask){
    int lane = threadIdx.x & 31;
    int e = (blockIdx.x * blockDim.x + threadIdx.x) * 4;
    if (e >= ET) return;
    int fl = g_mflag;
    int mode = (fl & 1) ? 2 : ((fl & 2) ? 0 : 1);

    int sel[4];
    if (mode == 0){
        uchar4 mv = *(const uchar4*)((const unsigned char*)mask + e);
        sel[0] = mv.x != 0; sel[1] = mv.y != 0; sel[2] = mv.z != 0; sel[3] = mv.w != 0;
    } else if (mode == 1){
        int4 mv = *(const int4*)((const int*)mask + e);
        sel[0] = mv.x != 0; sel[1] = mv.y != 0; sel[2] = mv.z != 0; sel[3] = mv.w != 0;
    } else {
        float4 mv = *(const float4*)((const float*)mask + e);
        sel[0] = mv.x != 0.f; sel[1] = mv.y != 0.f; sel[2] = mv.z != 0.f; sel[3] = mv.w != 0.f;
    }

    int4   tg = *(const int4*)(eidx + ET + e);
    int4   gb = *(const int4*)(ebatch + e);
    float4 sh = *(const float4*)(g_logits + e);

    float lp[4];
    lp[0] = sel[0] ? (sh.x - g_tsum[tg.x]) : 0.0f;
    lp[1] = sel[1] ? (sh.y - g_tsum[tg.y]) : 0.0f;
    lp[2] = sel[2] ? (sh.z - g_tsum[tg.z]) : 0.0f;
    lp[3] = sel[3] ? (sh.w - g_tsum[tg.w]) : 0.0f;
    int gbs[4] = {gb.x, gb.y, gb.z, gb.w};

    float v = 0.0f; int c = 0;
    int key = gbs[0];
    #pragma unroll
    for (int j = 0; j < 4; j++){
        if (gbs[j] == key){ v += lp[j]; c += sel[j]; }
        else if (sel[j]){
            atomicAdd(&g_logpb[gbs[j]], lp[j]);
            atomicAdd(&g_selcnt[gbs[j]], 1);
        }
    }

    #pragma unroll
    for (int off = 1; off < 32; off <<= 1){
        float ov = __shfl_down_sync(0xFFFFFFFFu, v, off);
        int   oc = __shfl_down_sync(0xFFFFFFFFu, c, off);
        int   ok = __shfl_down_sync(0xFFFFFFFFu, key, off);
        if (lane + off < 32 && ok == key){ v += ov; c += oc; }
    }
    int prevk = __shfl_up_sync(0xFFFFFFFFu, key, 1);
    bool leader = (lane == 0) || (prevk != key);
    if (leader && c > 0){
        atomicAdd(&g_logpb[key], v);
        atomicAdd(&g_selcnt[key], c);
    }
}

// ---------------- final ----------------
__global__ __launch_bounds__(1024) void k_final(float* __restrict__ out){
    __shared__ float rs[32];
    __shared__ int   ri[32];
    int t = threadIdx.x;
    float lp = g_logpb[t];
    int   c  = g_selcnt[t];
    float v = (c > 0) ? -lp : 0.0f;
    int   h = (c > 0) ? 1 : 0;
    #pragma unroll
    for (int o = 16; o > 0; o >>= 1){
        v += __shfl_xor_sync(0xFFFFFFFFu, v, o);
        h += __shfl_xor_sync(0xFFFFFFFFu, h, o);
    }
    if ((t & 31) == 0){ rs[t >> 5] = v; ri[t >> 5] = h; }
    __syncthreads();
    if (t < 32){
        float v2 = rs[t]; int h2 = ri[t];
        #pragma unroll
        for (int o = 16; o > 0; o >>= 1){
            v2 += __shfl_xor_sync(0xFFFFFFFFu, v2, o);
            h2 += __shfl_xor_sync(0xFFFFFFFFu, h2, o);
        }
        if (t == 0){ rs[0] = v2; ri[0] = h2; }
    }
    __syncthreads();
    float pbn = rs[0] / fmaxf((float)ri[0], 1.0f);
    out[t * 3 + 1] = lp;
    out[t * 3 + 2] = pbn;
}

// ---------------- launch ----------------
extern "C" void kernel_launch(void* const* d_in, const int* in_sizes, int n_in,
                              void* d_out, int out_size)
{
    int iN, iQ, iE, iLN1G, iLN1B, iZW1, iZB1, iZW2, iZB2,
        iCW1, iCB1, iCW2, iCB2, iBLG, iBLB, iBW1, iBB1, iBW2, iBB2,
        iLOC, iPTR, iEB, iMASK, iEIDX;
    if (in_sizes[3] == 4096){
        iN=0; iQ=1; iE=2; iLOC=3; iPTR=4; iEB=5; iMASK=6; iEIDX=7;
        iLN1G=8; iLN1B=9; iZW1=10; iZB1=11; iZW2=12; iZB2=13;
        iCW1=14; iCB1=15; iCW2=16; iCB2=17;
        iBLG=18; iBLB=19; iBW1=20; iBB1=21; iBW2=22; iBB2=23;
    } else {
        iN=0; iQ=1; iE=2;
        iLN1G=3; iLN1B=4; iZW1=5; iZB1=6; iZW2=7; iZB2=8;
        iCW1=9; iCB1=10; iCW2=11; iCB2=12;
        iBLG=13; iBLB=14; iBW1=15; iBB1=16; iBW2=17; iBB2=18;
        iLOC=19; iPTR=20; iEB=21; iMASK=22; iEIDX=23;
    }

    const float* node = (const float*)d_in[iN];
    const float* ques = (const float*)d_in[iQ];
    const float* etok = (const float*)d_in[iE];
    const float* ln1g = (const float*)d_in[iLN1G];
    const float* ln1b = (const float*)d_in[iLN1B];
    const float* zw1  = (const float*)d_in[iZW1];
    const float* zb1  = (const float*)d_in[iZB1];
    const float* zw2  = (const float*)d_in[iZW2];
    const float* zb2  = (const float*)d_in[iZB2];
    const float* cw1  = (const float*)d_in[iCW1];
    const float* cb1  = (const float*)d_in[iCB1];
    const float* cw2  = (const float*)d_in[iCW2];
    const float* cb2  = (const float*)d_in[iCB2];
    const float* blng = (const float*)d_in[iBLG];
    const float* blnb = (const float*)d_in[iBLB];
    const float* bw1  = (const float*)d_in[iBW1];
    const float* bb1  = (const float*)d_in[iBB1];
    const float* bw2  = (const float*)d_in[iBW2];
    const float* bb2  = (const float*)d_in[iBB2];
    const int* locals = (const int*)d_in[iLOC];
    const int* ptr    = (const int*)d_in[iPTR];
    const int* ebatch = (const int*)d_in[iEB];
    const void* mask  = (const void*)d_in[iMASK];
    const int* eidx   = (const int*)d_in[iEIDX];
    float* out = (float*)d_out;

    cudaFuncSetAttribute(k_main, cudaFuncAttributeMaxDynamicSharedMemorySize, MAIN_SMEM);

    k_prep<<<(NN + 255) / 256, 256>>>((const unsigned*)mask, bw1);
    k_main<<<NG + EDGE_BLKS, 256, MAIN_SMEM>>>(node, ques, etok, blng, blnb,
                                               bb1, bw2, bb2, ebatch, eidx,
                                               ln1g, ln1b, zw1, zb1, zw2, zb2,
                                               cw1, cb1, cw2, cb2, locals, ptr, out);
    k_log<<<(NN + 255) / 256, 256>>>();
    k_pass3<<<(ET / 4 + 255) / 256, 256>>>(eidx, ebatch, mask);
    k_final<<<1, 1024>>>(out);
}